// round 4
// baseline (speedup 1.0000x reference)
#include <cuda_runtime.h>
#include <cstdint>

#define Bb 256
#define Ss 512
#define BSF (Bb*Ss*64)
#define NCTA 64
#define NC 5            // cached weight quads per K-half (of 32)

typedef unsigned long long u64;

// ---------------- device scratch ----------------
__device__ __align__(16) float g_Wg[131072];   // k-pair-interleaved [Wih|Whh]^T
__device__ float g_dinv[Ss];
__device__ float g_lossbuf[NCTA];
__device__ int   g_ctr = 0;

// ---------------- helpers ----------------
__device__ __forceinline__ u64 f2fma(u64 a, u64 b, u64 c){
    u64 d;
    asm("fma.rn.f32x2 %0, %1, %2, %3;" : "=l"(d) : "l"(a), "l"(b), "l"(c));
    return d;
}
__device__ __forceinline__ float flo(u64 v){ return __uint_as_float((unsigned)v); }
__device__ __forceinline__ float fhi(u64 v){ return __uint_as_float((unsigned)(v>>32)); }
__device__ __forceinline__ float sigf(float v){ return __fdividef(1.f, 1.f + __expf(-v)); }
__device__ __forceinline__ float tanhf_(float v){ return __fdividef(2.f, 1.f + __expf(-2.f*v)) - 1.f; }

// ---------------- prep: transpose gates weights + per-step denoms ----------------
__global__ void k_prep(const float* __restrict__ Wih, const float* __restrict__ Whh,
                       const float* __restrict__ m){
    int bid = blockIdx.x, t = threadIdx.x;
    if (bid < 512){
        int id  = bid * 256 + t;
        int kp  = id >> 10;
        int rem = id & 1023;
        int j   = rem >> 1;
        int e   = rem & 1;
        int k   = (kp << 1) | e;
        g_Wg[id] = (k < 128) ? Wih[(j << 7) + k] : Whh[(j << 7) + (k - 128)];
    } else {
        __shared__ float red[256];
        int l = bid - 512;
        int f = t & 63, rb = t >> 6;
        float s = 0.f;
        for (int b = rb; b < Bb; b += 4)
            s += m[(((b << 9) + l) << 6) + f];
        red[t] = s; __syncthreads();
        for (int o = 128; o > 0; o >>= 1){ if (t < o) red[t] += red[t + o]; __syncthreads(); }
        if (t == 0) g_dinv[l] = 1.0f / (red[0] + 1e-5f);
        if (l == 0 && t == 0) g_ctr = 0;
    }
}

// ---------------- smem layout (float offsets) ----------------
#define OFF_WDH   0        // [128][68]
#define OFF_WTR   8704     // [64][132]
#define OFF_WFR   17152    // [64][68] diag zeroed
#define OFF_WWC   21504    // [64][132]
#define OFF_DWDM  29952
#define OFF_BDH   30016
#define OFF_BDM   30144
#define OFF_BTR   30208
#define OFF_BFR   30272
#define OFF_BWC   30336
#define OFF_BIHH  30400    // [512]
#define OFF_DINV  30912    // [512]
#define OFF_A     31424    // [4][264]: [0:64) cl_c, [64:128) ml, [128:256) h
#define OFF_TL    32480    // [4][72]
#define OFF_GM    32768
#define OFF_XC    33056
#define OFF_XL    33344
#define OFF_G     33632    // [4][512]
#define OFF_RED   35680    // [512]
#define OFF_WG    36192    // [2][NC][2048]
#define SMEM_FLOATS (36192 + 2*NC*2048)
#define SMEM_BYTES  (SMEM_FLOATS * 4)

// ---------------- main persistent recurrence: 64 CTAs x 512 threads ----------------
__global__ void __launch_bounds__(512, 1)
k_main(const float* __restrict__ x, const float* __restrict__ m, const float* __restrict__ tt,
       const float* __restrict__ Wdh, const float* __restrict__ bdh,
       const float* __restrict__ Wdm, const float* __restrict__ bdm,
       const float* __restrict__ Wtr, const float* __restrict__ btr,
       const float* __restrict__ Wfr, const float* __restrict__ bfr,
       const float* __restrict__ Wwc, const float* __restrict__ bwc,
       const float* __restrict__ bih, const float* __restrict__ bhh,
       float* __restrict__ out, int wloss)
{
    extern __shared__ float sm[];
    const int t  = threadIdx.x;
    const int b0 = blockIdx.x << 2;

    // ---- one-time smem fills ----
    for (int i = t; i < 128*64; i += 512) sm[OFF_WDH + (i>>6)*68  + (i&63)]  = Wdh[i];
    for (int i = t; i < 64*128; i += 512) sm[OFF_WTR + (i>>7)*132 + (i&127)] = Wtr[i];
    for (int i = t; i < 64*64;  i += 512){ int r = i>>6, c = i&63;
        sm[OFF_WFR + r*68 + c] = (r == c) ? 0.f : Wfr[i]; }
    for (int i = t; i < 64*128; i += 512) sm[OFF_WWC + (i>>7)*132 + (i&127)] = Wwc[i];
    if (t < 64){
        sm[OFF_DWDM + t] = Wdm[t*64 + t];
        sm[OFF_BDM + t] = bdm[t]; sm[OFF_BTR + t] = btr[t];
        sm[OFF_BFR + t] = bfr[t]; sm[OFF_BWC + t] = bwc[t];
    }
    if (t < 128) sm[OFF_BDH + t] = bdh[t];
    if (t < 512){
        sm[OFF_BIHH + t] = bih[t] + bhh[t];
        sm[OFF_DINV + t] = g_dinv[t];
    }
    for (int i = t; i < 2*NC*2048; i += 512){
        int half = i / (NC*2048), rem = i % (NC*2048);
        sm[OFF_WG + i] = g_Wg[half*65536 + rem];
    }
    // zero h
    sm[OFF_A + (t>>7)*264 + 128 + (t&127)] = 0.f;

    // ---- thread maps ----
    const int fl = t & 63,  rl = (t >> 6) & 3;   // staging map (same for both halves)
    const int jg = t >> 2,  rg = t & 3;          // phase A map
    const int fe = t >> 3,  re = (t >> 1) & 3;   // phase B/C map
    const int kh = t & 1;                        // K-half split
    const int cp = t >> 1;                       // phase D col-pair
    const int gtc = cp >> 6;                     // gate type
    const int rE = t >> 7,  jE = t & 127;        // phase E map

    const int inb = ((b0 + rl) << 15) + fl;
    if (t < 256){
        sm[OFF_XL + rl*72 + fl] = x[inb];
        sm[OFF_A  + rl*264 + 64 + fl] = m[inb];
    } else {
        sm[OFF_TL + rl*72 + fl] = tt[inb];
    }
    __syncthreads();

    float cE = 0.f, lacc = 0.f;
    float xn = 0.f, mn = 0.f, tn = 0.f;
    const float* __restrict__ wgb = g_Wg + (cp << 2);
    const float* __restrict__ wsb = sm + OFF_WG + kh*(NC*2048) + (cp << 2);

    #pragma unroll 1
    for (int l = 0; l < Ss; ++l){
        const float dinv = sm[OFF_DINV + l];

        // ===== A: gamma_h (512 outputs) + gamma_m (t<256) =====
        {
            const float* wr = sm + OFF_WDH + jg*68;
            const float* ta = sm + OFF_TL + rg*72;
            u64 S0 = 0, S1 = 0;
            #pragma unroll
            for (int q = 0; q < 16; ++q){
                ulonglong2 w = *(const ulonglong2*)(wr + (q<<2));
                ulonglong2 u = *(const ulonglong2*)(ta + (q<<2));
                S0 = f2fma(w.x, u.x, S0); S1 = f2fma(w.y, u.y, S1);
            }
            float a = flo(S0)+fhi(S0)+flo(S1)+fhi(S1) + sm[OFF_BDH + jg];
            sm[OFF_A + rg*264 + 128 + jg] *= __expf(-fmaxf(a, 0.f));
            if (t < 256){
                float tl_ = sm[OFF_TL + rg*72 + jg];   // jg=t>>2<64, rg=t&3 here
                float gm = __expf(-fmaxf(fmaf(tl_, sm[OFF_DWDM + jg], sm[OFF_BDM + jg]), 0.f));
                sm[OFF_GM + rg*72 + jg] = gm;
            }
        }
        __syncthreads();

        // ===== B: xl_hat (k-split by kh, shfl combine) =====
        float xh, xlv, mlv, dmv;
        {
            const float* wr = sm + OFF_WTR + fe*132 + (kh<<6);
            const float* hr = sm + OFF_A + re*264 + 128 + (kh<<6);
            u64 S0 = 0, S1 = 0;
            #pragma unroll
            for (int q = 0; q < 16; ++q){
                ulonglong2 w = *(const ulonglong2*)(wr + (q<<2));
                ulonglong2 u = *(const ulonglong2*)(hr + (q<<2));
                S0 = f2fma(w.x, u.x, S0); S1 = f2fma(w.y, u.y, S1);
            }
            float s = flo(S0)+fhi(S0)+flo(S1)+fhi(S1);
            s += __shfl_xor_sync(0xffffffffu, s, 1);
            xh  = s + sm[OFF_BTR + fe];
            xlv = sm[OFF_XL + re*72 + fe];
            mlv = sm[OFF_A + re*264 + 64 + fe];
            dmv = mlv * dinv;
            if (kh == 0){
                float d = xlv - xh;
                lacc = fmaf(d*d, dmv, lacc);
                sm[OFF_XC + re*72 + fe] = fmaf(mlv, d, xh);
            }
        }
        __syncthreads();

        // ===== C: z, beta, cl_hat, cl_c, loss (k-split, shfl combine) =====
        {
            const float* wr = sm + OFF_WFR + fe*68 + (kh<<5);
            const float* xr = sm + OFF_XC + re*72 + (kh<<5);
            u64 S0 = 0, S1 = 0;
            #pragma unroll
            for (int q = 0; q < 8; ++q){
                ulonglong2 w = *(const ulonglong2*)(wr + (q<<2));
                ulonglong2 u = *(const ulonglong2*)(xr + (q<<2));
                S0 = f2fma(w.x, u.x, S0); S1 = f2fma(w.y, u.y, S1);
            }
            float z = flo(S0)+fhi(S0)+flo(S1)+fhi(S1);
            z += __shfl_xor_sync(0xffffffffu, z, 1);
            z += sm[OFF_BFR + fe];

            const float* wc = sm + OFF_WWC + fe*132 + (kh<<6);
            const float* ur = kh ? (sm + OFF_A + re*264 + 64) : (sm + OFF_GM + re*72);
            u64 T0 = 0, T1 = 0;
            #pragma unroll
            for (int q = 0; q < 16; ++q){
                ulonglong2 w = *(const ulonglong2*)(wc + (q<<2));
                ulonglong2 u = *(const ulonglong2*)(ur + (q<<2));
                T0 = f2fma(w.x, u.x, T0); T1 = f2fma(w.y, u.y, T1);
            }
            float bt = flo(T0)+fhi(T0)+flo(T1)+fhi(T1);
            bt += __shfl_xor_sync(0xffffffffu, bt, 1);
            bt += sm[OFF_BWC + fe];

            if (kh == 0){
                float d2 = xlv - z;
                lacc = fmaf(d2*d2, dmv, lacc);
                float ch = fmaf(bt, z - xh, xh);
                float d3 = xlv - ch;
                lacc = fmaf(d3*d3, dmv, lacc);
                sm[OFF_A + re*264 + fe] = fmaf(mlv, d3, ch);   // cl_c
            }
        }
        __syncthreads();

        // ===== D: gates GEMM (col-pair x 4 rows x K/2) + prefetch + imputation store =====
        {
            int ln = (l < Ss-1) ? (l + 1) : l;
            if (t < 256){
                xn = x[inb + (ln << 6)];
                mn = m[inb + (ln << 6)];
            } else {
                tn = tt[inb + (ln << 6)];
                out[inb + (l << 6)] = sm[OFF_A + rl*264 + fl];
            }

            u64 P[4] = {0,0,0,0}, Q[4] = {0,0,0,0};
            const float* a0p = sm + OFF_A;

            #pragma unroll
            for (int i = 0; i < NC; ++i){
                const float* wp = wsb + (i << 11);
                ulonglong2 w0 = *(const ulonglong2*)wp;
                ulonglong2 w1 = *(const ulonglong2*)(wp + 1024);
                const int ko = ((kh << 5) + i) << 2;
                ulonglong2 a0 = *(const ulonglong2*)(a0p +       ko);
                ulonglong2 a1 = *(const ulonglong2*)(a0p + 264 + ko);
                ulonglong2 a2 = *(const ulonglong2*)(a0p + 528 + ko);
                ulonglong2 a3 = *(const ulonglong2*)(a0p + 792 + ko);
                P[0]=f2fma(w0.x,a0.x,P[0]); Q[0]=f2fma(w0.y,a0.x,Q[0]);
                P[0]=f2fma(w1.x,a0.y,P[0]); Q[0]=f2fma(w1.y,a0.y,Q[0]);
                P[1]=f2fma(w0.x,a1.x,P[1]); Q[1]=f2fma(w0.y,a1.x,Q[1]);
                P[1]=f2fma(w1.x,a1.y,P[1]); Q[1]=f2fma(w1.y,a1.y,Q[1]);
                P[2]=f2fma(w0.x,a2.x,P[2]); Q[2]=f2fma(w0.y,a2.x,Q[2]);
                P[2]=f2fma(w1.x,a2.y,P[2]); Q[2]=f2fma(w1.y,a2.y,Q[2]);
                P[3]=f2fma(w0.x,a3.x,P[3]); Q[3]=f2fma(w0.y,a3.x,Q[3]);
                P[3]=f2fma(w1.x,a3.y,P[3]); Q[3]=f2fma(w1.y,a3.y,Q[3]);
            }
            #pragma unroll 3
            for (int i = NC; i < 32; ++i){
                const int kp2 = (kh << 5) + i;
                const float* wp = wgb + (kp2 << 11);
                ulonglong2 w0 = *(const ulonglong2*)wp;
                ulonglong2 w1 = *(const ulonglong2*)(wp + 1024);
                const int ko = kp2 << 2;
                ulonglong2 a0 = *(const ulonglong2*)(a0p +       ko);
                ulonglong2 a1 = *(const ulonglong2*)(a0p + 264 + ko);
                ulonglong2 a2 = *(const ulonglong2*)(a0p + 528 + ko);
                ulonglong2 a3 = *(const ulonglong2*)(a0p + 792 + ko);
                P[0]=f2fma(w0.x,a0.x,P[0]); Q[0]=f2fma(w0.y,a0.x,Q[0]);
                P[0]=f2fma(w1.x,a0.y,P[0]); Q[0]=f2fma(w1.y,a0.y,Q[0]);
                P[1]=f2fma(w0.x,a1.x,P[1]); Q[1]=f2fma(w0.y,a1.x,Q[1]);
                P[1]=f2fma(w1.x,a1.y,P[1]); Q[1]=f2fma(w1.y,a1.y,Q[1]);
                P[2]=f2fma(w0.x,a2.x,P[2]); Q[2]=f2fma(w0.y,a2.x,Q[2]);
                P[2]=f2fma(w1.x,a2.y,P[2]); Q[2]=f2fma(w1.y,a2.y,Q[2]);
                P[3]=f2fma(w0.x,a3.x,P[3]); Q[3]=f2fma(w0.y,a3.x,Q[3]);
                P[3]=f2fma(w1.x,a3.y,P[3]); Q[3]=f2fma(w1.y,a3.y,Q[3]);
            }

            float b0f = sm[OFF_BIHH + (cp<<1)];
            float b1f = sm[OFF_BIHH + (cp<<1) + 1];
            #pragma unroll
            for (int r = 0; r < 4; ++r){
                float v0 = flo(P[r]) + fhi(P[r]);
                float v1 = flo(Q[r]) + fhi(Q[r]);
                v0 += __shfl_xor_sync(0xffffffffu, v0, 1);
                v1 += __shfl_xor_sync(0xffffffffu, v1, 1);
                if (kh == 0){
                    v0 += b0f; v1 += b1f;
                    if (gtc == 2){ v0 = tanhf_(v0); v1 = tanhf_(v1); }
                    else         { v0 = sigf(v0);   v1 = sigf(v1);   }
                    *(float2*)(sm + OFF_G + (r << 9) + (cp << 1)) = make_float2(v0, v1);
                }
            }
        }
        __syncthreads();

        // ===== E: LSTM combine (512 outputs, c in reg) + stage next inputs =====
        {
            const float* gA = sm + OFF_G + rE*512;
            float gi = gA[jE], gf = gA[128+jE], gg = gA[256+jE], go = gA[384+jE];
            cE = fmaf(gf, cE, gi*gg);
            sm[OFF_A + rE*264 + 128 + jE] = go * tanhf_(cE);
            if (t < 256){
                sm[OFF_XL + rl*72 + fl] = xn;
                sm[OFF_A  + rl*264 + 64 + fl] = mn;
            } else {
                sm[OFF_TL + rl*72 + fl] = tn;
            }
        }
        __syncthreads();
    }

    // ---- deterministic loss reduction + inter-CTA finish ----
    sm[OFF_RED + t] = lacc; __syncthreads();
    for (int o = 256; o > 0; o >>= 1){ if (t < o) sm[OFF_RED+t] += sm[OFF_RED+t+o]; __syncthreads(); }
    if (t == 0){
        g_lossbuf[blockIdx.x] = sm[OFF_RED];
        __threadfence();
        atomicAdd(&g_ctr, 1);
        if (blockIdx.x == 0){
            while (atomicAdd(&g_ctr, 0) < NCTA) { }
            float s = 0.f;
            #pragma unroll 1
            for (int i = 0; i < NCTA; ++i) s += ((volatile float*)g_lossbuf)[i];
            if (wloss) out[BSF] = s * (1.0f / (float)Ss);
            g_ctr = 0;
        }
    }
}

// ---------------- launcher ----------------
extern "C" void kernel_launch(void* const* d_in, const int* in_sizes, int n_in,
                              void* d_out, int out_size) {
    const float* x   = (const float*)d_in[0];
    const float* m   = (const float*)d_in[1];
    const float* tt  = (const float*)d_in[2];
    const float* Wdh = (const float*)d_in[3];
    const float* bdh = (const float*)d_in[4];
    const float* Wdm = (const float*)d_in[5];
    const float* bdm = (const float*)d_in[6];
    const float* Wtr = (const float*)d_in[7];
    const float* btr = (const float*)d_in[8];
    const float* Wfr = (const float*)d_in[9];
    const float* bfr = (const float*)d_in[10];
    const float* Wwc = (const float*)d_in[11];
    const float* bwc = (const float*)d_in[12];
    const float* Wih = (const float*)d_in[13];
    const float* Whh = (const float*)d_in[14];
    const float* bih = (const float*)d_in[15];
    const float* bhh = (const float*)d_in[16];
    float* out = (float*)d_out;

    cudaFuncSetAttribute(k_main, cudaFuncAttributeMaxDynamicSharedMemorySize, SMEM_BYTES);

    k_prep<<<1024, 256>>>(Wih, Whh, m);
    k_main<<<NCTA, 512, SMEM_BYTES>>>(x, m, tt, Wdh, bdh, Wdm, bdm, Wtr, btr,
                                      Wfr, bfr, Wwc, bwc, bih, bhh, out,
                                      (out_size > BSF) ? 1 : 0);
}

// round 8
// speedup vs baseline: 1.4094x; 1.4094x over previous
#include <cuda_runtime.h>
#include <cstdint>

#define Bb 256
#define Ss 512
#define BSF (Bb*Ss*64)
#define NCTA 64
#define NCQ 10          // k-quads cached in smem (of 64)

typedef unsigned long long u64;

// ---------------- device scratch ----------------
__device__ __align__(16) float g_Wg[131072];   // [kq][j][4] gates weights, k=4kq+e
__device__ float g_dinv[Ss];
__device__ float g_lossbuf[NCTA];
__device__ int   g_ctr = 0;

// ---------------- helpers ----------------
__device__ __forceinline__ u64 f2fma(u64 a, u64 b, u64 c){
    u64 d;
    asm("fma.rn.f32x2 %0, %1, %2, %3;" : "=l"(d) : "l"(a), "l"(b), "l"(c));
    return d;
}
__device__ __forceinline__ float flo(u64 v){ return __uint_as_float((unsigned)v); }
__device__ __forceinline__ float fhi(u64 v){ return __uint_as_float((unsigned)(v>>32)); }
__device__ __forceinline__ float sigf(float v){ return __fdividef(1.f, 1.f + __expf(-v)); }
__device__ __forceinline__ float tanhf_(float v){ return __fdividef(2.f, 1.f + __expf(-2.f*v)) - 1.f; }

// ---------------- prep: gates weights -> [kq][j][4]  + per-step denoms ----------------
__global__ void k_prep(const float* __restrict__ Wih, const float* __restrict__ Whh,
                       const float* __restrict__ m){
    int bid = blockIdx.x, t = threadIdx.x;
    if (bid < 512){
        int id  = bid * 256 + t;
        int kq  = id >> 11;
        int rem = id & 2047;
        int j   = rem >> 2;
        int e   = rem & 3;
        int k   = (kq << 2) | e;
        g_Wg[id] = (k < 128) ? Wih[(j << 7) + k] : Whh[(j << 7) + (k - 128)];
    } else {
        __shared__ float red[256];
        int l = bid - 512;
        int f = t & 63, rb = t >> 6;
        float s = 0.f;
        for (int b = rb; b < Bb; b += 4)
            s += m[(((b << 9) + l) << 6) + f];
        red[t] = s; __syncthreads();
        for (int o = 128; o > 0; o >>= 1){ if (t < o) red[t] += red[t + o]; __syncthreads(); }
        if (t == 0) g_dinv[l] = 1.0f / (red[0] + 1e-5f);
        if (l == 0 && t == 0) g_ctr = 0;
    }
}

// ---------------- smem layout (float offsets) ----------------
#define OFF_WDH   0        // [128][68]
#define OFF_WTR   8704     // [64][132]
#define OFF_WFR   17152    // [64][68] diag zeroed
#define OFF_WWC   21504    // [64][132]
#define OFF_DWDM  29952
#define OFF_BDH   30016
#define OFF_BDM   30144
#define OFF_BTR   30208
#define OFF_BFR   30272
#define OFF_BWC   30336
#define OFF_BIHH  30400    // [512]
#define OFF_DINV  30912    // [512]
#define OFF_A     31424    // [4][264]: [0:64) cl_c, [64:128) ml, [128:256) h
#define OFF_TL    32480    // [4][72]
#define OFF_GM    32768    // [4][72]
#define OFF_XC    33056    // [4][72]
#define OFF_XL    33344    // [4][72]
#define OFF_BT    33632    // [4][72] beta
#define OFF_G     33920    // [4][512]
#define OFF_RED   35968    // [512]
#define OFF_WG    36480    // [NCQ][512][4]
#define SMEM_FLOATS (36480 + NCQ*2048)
#define SMEM_BYTES  (SMEM_FLOATS * 4)

// ---------------- main persistent recurrence: 64 CTAs x 512 threads ----------------
__global__ void __launch_bounds__(512, 1)
k_main(const float* __restrict__ x, const float* __restrict__ m, const float* __restrict__ tt,
       const float* __restrict__ Wdh, const float* __restrict__ bdh,
       const float* __restrict__ Wdm, const float* __restrict__ bdm,
       const float* __restrict__ Wtr, const float* __restrict__ btr,
       const float* __restrict__ Wfr, const float* __restrict__ bfr,
       const float* __restrict__ Wwc, const float* __restrict__ bwc,
       const float* __restrict__ bih, const float* __restrict__ bhh,
       float* __restrict__ out, int wloss)
{
    extern __shared__ float sm[];
    const int t  = threadIdx.x;
    const int b0 = blockIdx.x << 2;

    // ---- one-time smem fills ----
    for (int i = t; i < 128*64; i += 512) sm[OFF_WDH + (i>>6)*68  + (i&63)]  = Wdh[i];
    for (int i = t; i < 64*128; i += 512) sm[OFF_WTR + (i>>7)*132 + (i&127)] = Wtr[i];
    for (int i = t; i < 64*64;  i += 512){ int r = i>>6, c = i&63;
        sm[OFF_WFR + r*68 + c] = (r == c) ? 0.f : Wfr[i]; }
    for (int i = t; i < 64*128; i += 512) sm[OFF_WWC + (i>>7)*132 + (i&127)] = Wwc[i];
    if (t < 64){
        sm[OFF_DWDM + t] = Wdm[t*64 + t];
        sm[OFF_BDM + t] = bdm[t]; sm[OFF_BTR + t] = btr[t];
        sm[OFF_BFR + t] = bfr[t]; sm[OFF_BWC + t] = bwc[t];
    }
    if (t < 128) sm[OFF_BDH + t] = bdh[t];
    sm[OFF_BIHH + t] = bih[t] + bhh[t];
    sm[OFF_DINV + t] = g_dinv[t];
    for (int i = t; i < NCQ*2048; i += 512) sm[OFF_WG + i] = g_Wg[i];
    // zero h
    sm[OFF_A + (t>>7)*264 + 128 + (t&127)] = 0.f;

    // ---- thread maps ----
    const int jg = t >> 2, rg = t & 3;          // A map (also gamma_m for t<256)
    const int fe = t >> 2, re = t & 3;          // B/C map (lower half)
    const int s_ = t & 255;                     // upper-half index
    const int fu = s_ >> 2, ru = s_ & 3;        // beta map (upper half)
    const int flu = s_ & 63, rlu = s_ >> 6;     // prefetch/staging map (upper half)
    const int flo_ = t & 63, rlo = (t >> 6) & 3;// out-store map (lower half)
    const int rE = t >> 7, jE = t & 127;        // E map
    const int gt_ = t >> 7;                     // gate type of col t

    const int inbU = ((b0 + rlu) << 15) + flu;  // upper threads' global base
    const int inbL = ((b0 + rlo) << 15) + flo_; // lower threads' global base

    float xn = 0.f, mn = 0.f, tn = 0.f;
    if (t >= 256){   // stage step-0 inputs
        sm[OFF_XL + rlu*72 + flu] = x[inbU];
        sm[OFF_A  + rlu*264 + 64 + flu] = m[inbU];
        sm[OFF_TL + rlu*72 + flu] = tt[inbU];
    }
    __syncthreads();

    float cE = 0.f, lacc = 0.f;
    const float* __restrict__ wgt = g_Wg + (t << 2);
    const float* __restrict__ wst = sm + OFF_WG + (t << 2);

    #pragma unroll 1
    for (int l = 0; l < Ss; ++l){
        const float dinv = sm[OFF_DINV + l];

        // ===== A: gamma_h (512 outputs) + gamma_m (t<256) =====
        {
            const float* wr = sm + OFF_WDH + jg*68;
            const float* ta = sm + OFF_TL + rg*72;
            u64 S0 = 0, S1 = 0;
            #pragma unroll
            for (int q = 0; q < 16; ++q){
                ulonglong2 w = *(const ulonglong2*)(wr + (q<<2));
                ulonglong2 u = *(const ulonglong2*)(ta + (q<<2));
                S0 = f2fma(w.x, u.x, S0); S1 = f2fma(w.y, u.y, S1);
            }
            float a = flo(S0)+fhi(S0)+flo(S1)+fhi(S1) + sm[OFF_BDH + jg];
            sm[OFF_A + rg*264 + 128 + jg] *= __expf(-fmaxf(a, 0.f));
            if (t < 256){
                float tl_ = sm[OFF_TL + rg*72 + jg];
                float gm = __expf(-fmaxf(fmaf(tl_, sm[OFF_DWDM + jg], sm[OFF_BDM + jg]), 0.f));
                sm[OFF_GM + rg*72 + jg] = gm;
            }
        }
        __syncthreads();

        // ===== B: lower = xl_hat;  upper = beta + prefetch next inputs =====
        float xh = 0.f, xlv = 0.f, mlv = 0.f, dmv = 0.f;
        if (t < 256){
            const float* wr = sm + OFF_WTR + fe*132;
            const float* hr = sm + OFF_A + re*264 + 128;
            u64 S0=0,S1=0,S2=0,S3=0;
            #pragma unroll
            for (int q = 0; q < 32; q += 2){
                ulonglong2 w0 = *(const ulonglong2*)(wr + (q<<2));
                ulonglong2 u0 = *(const ulonglong2*)(hr + (q<<2));
                ulonglong2 w1 = *(const ulonglong2*)(wr + ((q+1)<<2));
                ulonglong2 u1 = *(const ulonglong2*)(hr + ((q+1)<<2));
                S0 = f2fma(w0.x, u0.x, S0); S1 = f2fma(w0.y, u0.y, S1);
                S2 = f2fma(w1.x, u1.x, S2); S3 = f2fma(w1.y, u1.y, S3);
            }
            xh  = flo(S0)+fhi(S0)+flo(S1)+fhi(S1)+flo(S2)+fhi(S2)+flo(S3)+fhi(S3)
                + sm[OFF_BTR + fe];
            xlv = sm[OFF_XL + re*72 + fe];
            mlv = sm[OFF_A + re*264 + 64 + fe];
            dmv = mlv * dinv;
            float d = xlv - xh;
            lacc = fmaf(d*d, dmv, lacc);
            sm[OFF_XC + re*72 + fe] = fmaf(mlv, d, xh);
        } else {
            // prefetch next-step inputs (long latency, issued first)
            int ln = (l < Ss-1) ? (l + 1) : l;
            xn = x[inbU + (ln << 6)];
            mn = m[inbU + (ln << 6)];
            tn = tt[inbU + (ln << 6)];
            // beta = [gamma_m | ml] @ Wwc^T + bwc   (independent of xl_hat)
            const float* wc = sm + OFF_WWC + fu*132;
            const float* gr = sm + OFF_GM + ru*72;
            const float* mr = sm + OFF_A + ru*264 + 64;
            u64 T0=0,T1=0,T2=0,T3=0;
            #pragma unroll
            for (int q = 0; q < 16; ++q){
                ulonglong2 w0 = *(const ulonglong2*)(wc + (q<<2));
                ulonglong2 u0 = *(const ulonglong2*)(gr + (q<<2));
                ulonglong2 w1 = *(const ulonglong2*)(wc + 64 + (q<<2));
                ulonglong2 u1 = *(const ulonglong2*)(mr + (q<<2));
                T0 = f2fma(w0.x, u0.x, T0); T1 = f2fma(w0.y, u0.y, T1);
                T2 = f2fma(w1.x, u1.x, T2); T3 = f2fma(w1.y, u1.y, T3);
            }
            float bt = flo(T0)+fhi(T0)+flo(T1)+fhi(T1)+flo(T2)+fhi(T2)+flo(T3)+fhi(T3)
                     + sm[OFF_BWC + fu];
            sm[OFF_BT + ru*72 + fu] = bt;
        }
        __syncthreads();

        // ===== C: lower = z, cl_hat, cl_c, loss =====
        if (t < 256){
            const float* wr = sm + OFF_WFR + fe*68;
            const float* xr = sm + OFF_XC + re*72;
            u64 S0 = 0, S1 = 0;
            #pragma unroll
            for (int q = 0; q < 16; ++q){
                ulonglong2 w = *(const ulonglong2*)(wr + (q<<2));
                ulonglong2 u = *(const ulonglong2*)(xr + (q<<2));
                S0 = f2fma(w.x, u.x, S0); S1 = f2fma(w.y, u.y, S1);
            }
            float z = flo(S0)+fhi(S0)+flo(S1)+fhi(S1) + sm[OFF_BFR + fe];
            float bt = sm[OFF_BT + re*72 + fe];
            float d2 = xlv - z;
            lacc = fmaf(d2*d2, dmv, lacc);
            float ch = fmaf(bt, z - xh, xh);
            float d3 = xlv - ch;
            lacc = fmaf(d3*d3, dmv, lacc);
            sm[OFF_A + re*264 + fe] = fmaf(mlv, d3, ch);   // cl_c
        }
        __syncthreads();

        // ===== D: gates GEMM — col t, 4 rows, K=256 =====
        {
            u64 P0=0,P1=0,P2=0,P3=0,Q0=0,Q1=0,Q2=0,Q3=0;
            const float* a0p = sm + OFF_A;
            #pragma unroll
            for (int kq = 0; kq < NCQ; ++kq){
                ulonglong2 w = *(const ulonglong2*)(wst + (kq<<11));
                const int ko = kq << 2;
                ulonglong2 a0 = *(const ulonglong2*)(a0p +        ko);
                ulonglong2 a1 = *(const ulonglong2*)(a0p + 264 +  ko);
                ulonglong2 a2 = *(const ulonglong2*)(a0p + 528 +  ko);
                ulonglong2 a3 = *(const ulonglong2*)(a0p + 792 +  ko);
                P0 = f2fma(w.x, a0.x, P0); Q0 = f2fma(w.y, a0.y, Q0);
                P1 = f2fma(w.x, a1.x, P1); Q1 = f2fma(w.y, a1.y, Q1);
                P2 = f2fma(w.x, a2.x, P2); Q2 = f2fma(w.y, a2.y, Q2);
                P3 = f2fma(w.x, a3.x, P3); Q3 = f2fma(w.y, a3.y, Q3);
            }
            #pragma unroll 4
            for (int kq = NCQ; kq < 64; ++kq){
                ulonglong2 w = *(const ulonglong2*)(wgt + (kq<<11));
                const int ko = kq << 2;
                ulonglong2 a0 = *(const ulonglong2*)(a0p +        ko);
                ulonglong2 a1 = *(const ulonglong2*)(a0p + 264 +  ko);
                ulonglong2 a2 = *(const ulonglong2*)(a0p + 528 +  ko);
                ulonglong2 a3 = *(const ulonglong2*)(a0p + 792 +  ko);
                P0 = f2fma(w.x, a0.x, P0); Q0 = f2fma(w.y, a0.y, Q0);
                P1 = f2fma(w.x, a1.x, P1); Q1 = f2fma(w.y, a1.y, Q1);
                P2 = f2fma(w.x, a2.x, P2); Q2 = f2fma(w.y, a2.y, Q2);
                P3 = f2fma(w.x, a3.x, P3); Q3 = f2fma(w.y, a3.y, Q3);
            }
            float bb = sm[OFF_BIHH + t];
            float v0 = flo(P0)+fhi(P0)+flo(Q0)+fhi(Q0) + bb;
            float v1 = flo(P1)+fhi(P1)+flo(Q1)+fhi(Q1) + bb;
            float v2 = flo(P2)+fhi(P2)+flo(Q2)+fhi(Q2) + bb;
            float v3 = flo(P3)+fhi(P3)+flo(Q3)+fhi(Q3) + bb;
            if (gt_ == 2){ v0=tanhf_(v0); v1=tanhf_(v1); v2=tanhf_(v2); v3=tanhf_(v3); }
            else         { v0=sigf(v0);   v1=sigf(v1);   v2=sigf(v2);   v3=sigf(v3);   }
            sm[OFF_G +         t] = v0;
            sm[OFF_G +  512 +  t] = v1;
            sm[OFF_G + 1024 +  t] = v2;
            sm[OFF_G + 1536 +  t] = v3;
        }
        __syncthreads();

        // ===== E: LSTM combine (512 outputs) + out store / stage next inputs =====
        {
            const float* gA = sm + OFF_G + rE*512;
            float gi = gA[jE], gf = gA[128+jE], gg = gA[256+jE], go = gA[384+jE];
            cE = fmaf(gf, cE, gi*gg);
            sm[OFF_A + rE*264 + 128 + jE] = go * tanhf_(cE);
            if (t < 256){
                out[inbL + (l << 6)] = sm[OFF_A + rlo*264 + flo_];   // cl_c (post-C)
            } else {
                sm[OFF_XL + rlu*72 + flu] = xn;
                sm[OFF_A  + rlu*264 + 64 + flu] = mn;
                sm[OFF_TL + rlu*72 + flu] = tn;
            }
        }
        __syncthreads();
    }

    // ---- deterministic loss reduction + inter-CTA finish ----
    sm[OFF_RED + t] = lacc; __syncthreads();
    for (int o = 256; o > 0; o >>= 1){ if (t < o) sm[OFF_RED+t] += sm[OFF_RED+t+o]; __syncthreads(); }
    if (t == 0){
        g_lossbuf[blockIdx.x] = sm[OFF_RED];
        __threadfence();
        atomicAdd(&g_ctr, 1);
        if (blockIdx.x == 0){
            while (atomicAdd(&g_ctr, 0) < NCTA) { }
            float s = 0.f;
            #pragma unroll 1
            for (int i = 0; i < NCTA; ++i) s += ((volatile float*)g_lossbuf)[i];
            if (wloss) out[BSF] = s * (1.0f / (float)Ss);
            g_ctr = 0;
        }
    }
}

// ---------------- launcher ----------------
extern "C" void kernel_launch(void* const* d_in, const int* in_sizes, int n_in,
                              void* d_out, int out_size) {
    const float* x   = (const float*)d_in[0];
    const float* m   = (const float*)d_in[1];
    const float* tt  = (const float*)d_in[2];
    const float* Wdh = (const float*)d_in[3];
    const float* bdh = (const float*)d_in[4];
    const float* Wdm = (const float*)d_in[5];
    const float* bdm = (const float*)d_in[6];
    const float* Wtr = (const float*)d_in[7];
    const float* btr = (const float*)d_in[8];
    const float* Wfr = (const float*)d_in[9];
    const float* bfr = (const float*)d_in[10];
    const float* Wwc = (const float*)d_in[11];
    const float* bwc = (const float*)d_in[12];
    const float* Wih = (const float*)d_in[13];
    const float* Whh = (const float*)d_in[14];
    const float* bih = (const float*)d_in[15];
    const float* bhh = (const float*)d_in[16];
    float* out = (float*)d_out;

    cudaFuncSetAttribute(k_main, cudaFuncAttributeMaxDynamicSharedMemorySize, SMEM_BYTES);

    k_prep<<<1024, 256>>>(Wih, Whh, m);
    k_main<<<NCTA, 512, SMEM_BYTES>>>(x, m, tt, Wdh, bdh, Wdm, bdm, Wtr, btr,
                                      Wfr, bfr, Wwc, bwc, bih, bhh, out,
                                      (out_size > BSF) ? 1 : 0);
}

// round 10
// speedup vs baseline: 2.0637x; 1.4643x over previous
#include <cuda_runtime.h>
#include <cstdint>

#define Bb 256
#define Ss 512
#define BSF (Bb*Ss*64)
#define NCTA 128        // 2 batch rows per CTA -> 1 CTA per SM (smem-forced)
#define KPSM 11         // cached weight kp2-quads (of 64)

typedef unsigned long long u64;

// ---------------- device scratch ----------------
__device__ __align__(16) float g_Wg[131072];   // k-pair-interleaved [Wih|Whh]^T
__device__ float g_dinv[Ss];
__device__ float g_lossbuf[NCTA];
__device__ int   g_ctr = 0;

// ---------------- helpers ----------------
__device__ __forceinline__ u64 f2fma(u64 a, u64 b, u64 c){
    u64 d;
    asm("fma.rn.f32x2 %0, %1, %2, %3;" : "=l"(d) : "l"(a), "l"(b), "l"(c));
    return d;
}
__device__ __forceinline__ float flo(u64 v){ return __uint_as_float((unsigned)v); }
__device__ __forceinline__ float fhi(u64 v){ return __uint_as_float((unsigned)(v>>32)); }
__device__ __forceinline__ float sigf(float v){ return __fdividef(1.f, 1.f + __expf(-v)); }
__device__ __forceinline__ float tanhf_(float v){ return __fdividef(2.f, 1.f + __expf(-2.f*v)) - 1.f; }

// ---------------- prep: weight transpose + denoms ----------------
__global__ void k_prep(const float* __restrict__ Wih, const float* __restrict__ Whh,
                       const float* __restrict__ m){
    int bid = blockIdx.x, t = threadIdx.x;
    if (bid < 512){
        int id  = bid * 256 + t;
        int kp  = id >> 10;
        int rem = id & 1023;
        int j   = rem >> 1;
        int e   = rem & 1;
        int k   = (kp << 1) | e;
        g_Wg[id] = (k < 128) ? Wih[(j << 7) + k] : Whh[(j << 7) + (k - 128)];
    } else {
        __shared__ float red[256];
        int l = bid - 512;
        int f = t & 63, rb = t >> 6;
        float s = 0.f;
        for (int b = rb; b < Bb; b += 4)
            s += m[(((b << 9) + l) << 6) + f];
        red[t] = s; __syncthreads();
        for (int o = 128; o > 0; o >>= 1){ if (t < o) red[t] += red[t + o]; __syncthreads(); }
        if (t == 0) g_dinv[l] = 1.0f / (red[0] + 1e-5f);
        if (l == 0 && t == 0) g_ctr = 0;
    }
}

// ---------------- smem layout (float offsets), Bc = 2 ----------------
#define OFF_WDH   0        // [128][68]
#define OFF_WTR   8704     // [64][132]
#define OFF_WFR   17152    // [64][68] diag zeroed
#define OFF_WWC   21504    // [64][132]
#define OFF_DWDM  29952
#define OFF_BDH   30016    // [128]
#define OFF_BDM   30144
#define OFF_BTR   30208
#define OFF_BFR   30272
#define OFF_BWC   30336
#define OFF_BIHH  30400    // [512]
#define OFF_DINV  30912    // [512]
#define OFF_A     31424    // [2][264]: [0:64) cl_c, [64:128) ml, [128:256) h
#define OFF_TL    31952    // [2][72]
#define OFF_GM    32096    // [2][72]
#define OFF_XC    32240    // [2][72]
#define OFF_XL    32384    // [2][72]
#define OFF_G     32528    // [2][512]
#define OFF_RED   33552    // [256]
#define OFF_WG    33808    // [KPSM][2048]
#define SMEM_FLOATS (33808 + KPSM*2048)
#define SMEM_BYTES  (SMEM_FLOATS * 4)

// ---------------- main persistent recurrence: 128 CTAs x 256 threads ----------------
__global__ void __launch_bounds__(256, 1)
k_main(const float* __restrict__ x, const float* __restrict__ m, const float* __restrict__ tt,
       const float* __restrict__ Wdh, const float* __restrict__ bdh,
       const float* __restrict__ Wdm, const float* __restrict__ bdm,
       const float* __restrict__ Wtr, const float* __restrict__ btr,
       const float* __restrict__ Wfr, const float* __restrict__ bfr,
       const float* __restrict__ Wwc, const float* __restrict__ bwc,
       const float* __restrict__ bih, const float* __restrict__ bhh,
       float* __restrict__ out, int wloss)
{
    extern __shared__ float sm[];
    const int t  = threadIdx.x;
    const int b0 = blockIdx.x << 1;           // 2 batch rows per CTA

    // ---- one-time smem fills ----
    for (int i = t; i < 128*64; i += 256) sm[OFF_WDH + (i>>6)*68  + (i&63)]  = Wdh[i];
    for (int i = t; i < 64*128; i += 256) sm[OFF_WTR + (i>>7)*132 + (i&127)] = Wtr[i];
    for (int i = t; i < 64*64;  i += 256){ int r = i>>6, c = i&63;
        sm[OFF_WFR + r*68 + c] = (r == c) ? 0.f : Wfr[i]; }
    for (int i = t; i < 64*128; i += 256) sm[OFF_WWC + (i>>7)*132 + (i&127)] = Wwc[i];
    if (t < 64){
        sm[OFF_DWDM + t] = Wdm[t*64 + t];
        sm[OFF_BDM + t] = bdm[t]; sm[OFF_BTR + t] = btr[t];
        sm[OFF_BFR + t] = bfr[t]; sm[OFF_BWC + t] = bwc[t];
    }
    if (t < 128) sm[OFF_BDH + t] = bdh[t];
    for (int i = t; i < 512; i += 256){
        sm[OFF_BIHH + i] = bih[i] + bhh[i];
        sm[OFF_DINV + i] = g_dinv[i];
    }
    for (int i = t; i < KPSM*2048; i += 256) sm[OFF_WG + i] = g_Wg[i];
    // zero h: 2 x 128
    sm[OFF_A + (t>>7)*264 + 128 + (t&127)] = 0.f;

    // ---- thread maps ----
    const int fl = t & 63,  rl = (t >> 6) & 1;  // staging/out map (t<128 active)
    const int jA = t >> 1,  rA = t & 1;         // phase A gamma_h map (256 outputs)
    const int fe = t >> 2;                      // feature for B/C
    const int rb = (t >> 1) & 1;                // row for B/C
    const int kh = t & 1;                       // K-half split for B/C
    const int gt_ = t >> 6;                     // gate type of cols {2t,2t+1}
    const int rE = t >> 7,  jE = t & 127;       // phase E map

    const int inb = ((b0 + rl) << 15) + fl;     // (b0+rl)*S*F + fl
    if (t < 128){
        sm[OFF_XL + rl*72 + fl] = x[inb];
        sm[OFF_A  + rl*264 + 64 + fl] = m[inb];
        sm[OFF_TL + rl*72 + fl] = tt[inb];
    }
    __syncthreads();

    float cE = 0.f, lacc = 0.f;
    float xn = 0.f, mn = 0.f, tn = 0.f;
    const float* __restrict__ wgf = g_Wg + (t << 2);
    const int tx4 = t << 2;

    #pragma unroll 1
    for (int l = 0; l < Ss; ++l){
        const float dinv = sm[OFF_DINV + l];

        // ===== A: gamma_h (256 outputs, f32x2) + gamma_m (t<128) =====
        {
            const float* wr = sm + OFF_WDH + jA*68;
            const float* ta = sm + OFF_TL + rA*72;
            u64 S0 = 0, S1 = 0;
            #pragma unroll
            for (int q = 0; q < 16; ++q){
                ulonglong2 w = *(const ulonglong2*)(wr + (q<<2));
                ulonglong2 u = *(const ulonglong2*)(ta + (q<<2));
                S0 = f2fma(w.x, u.x, S0); S1 = f2fma(w.y, u.y, S1);
            }
            float a = flo(S0)+fhi(S0)+flo(S1)+fhi(S1) + sm[OFF_BDH + jA];
            sm[OFF_A + rA*264 + 128 + jA] *= __expf(-fmaxf(a, 0.f));
            if (t < 128){
                float tl_ = sm[OFF_TL + rl*72 + fl];
                float gm = __expf(-fmaxf(fmaf(tl_, sm[OFF_DWDM + fl], sm[OFF_BDM + fl]), 0.f));
                sm[OFF_GM + rl*72 + fl] = gm;
            }
        }
        __syncthreads();

        // ===== B: xl_hat (fe,rb; K-half split kh, shfl combine) =====
        float xh, xlv, mlv, dmv;
        {
            const float* wr = sm + OFF_WTR + fe*132 + (kh<<6);
            const float* hr = sm + OFF_A + rb*264 + 128 + (kh<<6);
            u64 S0 = 0, S1 = 0;
            #pragma unroll
            for (int q = 0; q < 16; ++q){
                ulonglong2 w = *(const ulonglong2*)(wr + (q<<2));
                ulonglong2 u = *(const ulonglong2*)(hr + (q<<2));
                S0 = f2fma(w.x, u.x, S0); S1 = f2fma(w.y, u.y, S1);
            }
            float s = flo(S0)+fhi(S0)+flo(S1)+fhi(S1);
            s += __shfl_xor_sync(0xffffffffu, s, 1);
            xh  = s + sm[OFF_BTR + fe];
            xlv = sm[OFF_XL + rb*72 + fe];
            mlv = sm[OFF_A + rb*264 + 64 + fe];
            dmv = mlv * dinv;
            if (kh == 0){
                float d = xlv - xh;
                lacc = fmaf(d*d, dmv, lacc);
                sm[OFF_XC + rb*72 + fe] = fmaf(mlv, d, xh);
            }
        }
        __syncthreads();

        // ===== C: z + beta (K-half split), combine, cl_c, loss =====
        {
            const float* wr = sm + OFF_WFR + fe*68 + (kh<<5);
            const float* xr = sm + OFF_XC + rb*72 + (kh<<5);
            u64 S0 = 0, S1 = 0;
            #pragma unroll
            for (int q = 0; q < 8; ++q){
                ulonglong2 w = *(const ulonglong2*)(wr + (q<<2));
                ulonglong2 u = *(const ulonglong2*)(xr + (q<<2));
                S0 = f2fma(w.x, u.x, S0); S1 = f2fma(w.y, u.y, S1);
            }
            float z = flo(S0)+fhi(S0)+flo(S1)+fhi(S1);
            z += __shfl_xor_sync(0xffffffffu, z, 1);
            z += sm[OFF_BFR + fe];

            const float* wc = sm + OFF_WWC + fe*132 + (kh<<6);
            const float* ur = kh ? (sm + OFF_A + rb*264 + 64) : (sm + OFF_GM + rb*72);
            u64 T0 = 0, T1 = 0;
            #pragma unroll
            for (int q = 0; q < 16; ++q){
                ulonglong2 w = *(const ulonglong2*)(wc + (q<<2));
                ulonglong2 u = *(const ulonglong2*)(ur + (q<<2));
                T0 = f2fma(w.x, u.x, T0); T1 = f2fma(w.y, u.y, T1);
            }
            float bt = flo(T0)+fhi(T0)+flo(T1)+fhi(T1);
            bt += __shfl_xor_sync(0xffffffffu, bt, 1);
            bt += sm[OFF_BWC + fe];

            if (kh == 0){
                float d2 = xlv - z;
                lacc = fmaf(d2*d2, dmv, lacc);
                float ch = fmaf(bt, z - xh, xh);
                float d3 = xlv - ch;
                lacc = fmaf(d3*d3, dmv, lacc);
                sm[OFF_A + rb*264 + fe] = fmaf(mlv, d3, ch);   // cl_c
            }
        }
        __syncthreads();

        // ===== D: gates GEMM (cols {2t,2t+1} x 2 rows x K=256) + prefetch + store =====
        {
            int ln = (l < Ss-1) ? (l + 1) : l;
            if (t < 128){
                xn = x[inb + (ln << 6)];
                mn = m[inb + (ln << 6)];
                tn = tt[inb + (ln << 6)];
                out[inb + (l << 6)] = sm[OFF_A + rl*264 + fl];   // coalesced cl_c store
            }

            u64 P0[2]={0,0}, P1[2]={0,0}, Q0[2]={0,0}, Q1[2]={0,0};
            const float* a0p = sm + OFF_A;

            #pragma unroll
            for (int kp2 = 0; kp2 < KPSM; ++kp2){
                const float* wp = sm + OFF_WG + (kp2 << 11) + tx4;
                ulonglong2 w0 = *(const ulonglong2*)wp;
                ulonglong2 w1 = *(const ulonglong2*)(wp + 1024);
                ulonglong2 a0 = *(const ulonglong2*)(a0p +       (kp2 << 2));
                ulonglong2 a1 = *(const ulonglong2*)(a0p + 264 + (kp2 << 2));
                P0[0]=f2fma(w0.x,a0.x,P0[0]); Q0[0]=f2fma(w0.y,a0.x,Q0[0]);
                P1[0]=f2fma(w1.x,a0.y,P1[0]); Q1[0]=f2fma(w1.y,a0.y,Q1[0]);
                P0[1]=f2fma(w0.x,a1.x,P0[1]); Q0[1]=f2fma(w0.y,a1.x,Q0[1]);
                P1[1]=f2fma(w1.x,a1.y,P1[1]); Q1[1]=f2fma(w1.y,a1.y,Q1[1]);
            }
            #pragma unroll 8
            for (int kp2 = KPSM; kp2 < 64; ++kp2){
                ulonglong2 w0 = *(const ulonglong2*)(wgf + (kp2 << 11));
                ulonglong2 w1 = *(const ulonglong2*)(wgf + (kp2 << 11) + 1024);
                ulonglong2 a0 = *(const ulonglong2*)(a0p +       (kp2 << 2));
                ulonglong2 a1 = *(const ulonglong2*)(a0p + 264 + (kp2 << 2));
                P0[0]=f2fma(w0.x,a0.x,P0[0]); Q0[0]=f2fma(w0.y,a0.x,Q0[0]);
                P1[0]=f2fma(w1.x,a0.y,P1[0]); Q1[0]=f2fma(w1.y,a0.y,Q1[0]);
                P0[1]=f2fma(w0.x,a1.x,P0[1]); Q0[1]=f2fma(w0.y,a1.x,Q0[1]);
                P1[1]=f2fma(w1.x,a1.y,P1[1]); Q1[1]=f2fma(w1.y,a1.y,Q1[1]);
            }
            float b0f = sm[OFF_BIHH + (t<<1)];
            float b1f = sm[OFF_BIHH + (t<<1) + 1];
            #pragma unroll
            for (int r = 0; r < 2; ++r){
                float v0 = (flo(P0[r]) + fhi(P0[r])) + (flo(P1[r]) + fhi(P1[r])) + b0f;
                float v1 = (flo(Q0[r]) + fhi(Q0[r])) + (flo(Q1[r]) + fhi(Q1[r])) + b1f;
                if (gt_ == 2){ v0 = tanhf_(v0); v1 = tanhf_(v1); }
                else         { v0 = sigf(v0);   v1 = sigf(v1);   }
                *(float2*)(sm + OFF_G + (r << 9) + (t << 1)) = make_float2(v0, v1);
            }
        }
        __syncthreads();

        // ===== E: LSTM combine (256 outputs, c in reg) + stage next inputs =====
        {
            const float* gA = sm + OFF_G + rE*512;
            float gi = gA[jE], gf = gA[128+jE], gg = gA[256+jE], go = gA[384+jE];
            cE = fmaf(gf, cE, gi*gg);
            sm[OFF_A + rE*264 + 128 + jE] = go * tanhf_(cE);
            if (t < 128){
                sm[OFF_XL + rl*72 + fl] = xn;
                sm[OFF_A  + rl*264 + 64 + fl] = mn;
                sm[OFF_TL + rl*72 + fl] = tn;
            }
        }
        __syncthreads();
    }

    // ---- deterministic loss reduction + inter-CTA finish (128 co-resident CTAs) ----
    sm[OFF_RED + t] = lacc; __syncthreads();
    for (int o = 128; o > 0; o >>= 1){ if (t < o) sm[OFF_RED+t] += sm[OFF_RED+t+o]; __syncthreads(); }
    if (t == 0){
        g_lossbuf[blockIdx.x] = sm[OFF_RED];
        __threadfence();
        atomicAdd(&g_ctr, 1);
        if (blockIdx.x == 0){
            while (atomicAdd(&g_ctr, 0) < NCTA) { }
            float s = 0.f;
            #pragma unroll 1
            for (int i = 0; i < NCTA; ++i) s += ((volatile float*)g_lossbuf)[i];
            if (wloss) out[BSF] = s * (1.0f / (float)Ss);
            g_ctr = 0;
        }
    }
}

// ---------------- launcher ----------------
extern "C" void kernel_launch(void* const* d_in, const int* in_sizes, int n_in,
                              void* d_out, int out_size) {
    const float* x   = (const float*)d_in[0];
    const float* m   = (const float*)d_in[1];
    const float* tt  = (const float*)d_in[2];
    const float* Wdh = (const float*)d_in[3];
    const float* bdh = (const float*)d_in[4];
    const float* Wdm = (const float*)d_in[5];
    const float* bdm = (const float*)d_in[6];
    const float* Wtr = (const float*)d_in[7];
    const float* btr = (const float*)d_in[8];
    const float* Wfr = (const float*)d_in[9];
    const float* bfr = (const float*)d_in[10];
    const float* Wwc = (const float*)d_in[11];
    const float* bwc = (const float*)d_in[12];
    const float* Wih = (const float*)d_in[13];
    const float* Whh = (const float*)d_in[14];
    const float* bih = (const float*)d_in[15];
    const float* bhh = (const float*)d_in[16];
    float* out = (float*)d_out;

    cudaFuncSetAttribute(k_main, cudaFuncAttributeMaxDynamicSharedMemorySize, SMEM_BYTES);

    k_prep<<<1024, 256>>>(Wih, Whh, m);
    k_main<<<NCTA, 256, SMEM_BYTES>>>(x, m, tt, Wdh, bdh, Wdm, bdm, Wtr, btr,
                                      Wfr, bfr, Wwc, bwc, bih, bhh, out,
                                      (out_size > BSF) ? 1 : 0);
}